// round 2
// baseline (speedup 1.0000x reference)
#include <cuda_runtime.h>

// Problem dims
#define BB 8
#define SS 2048
#define DMODEL 1024
#define HDIM 64
#define NHEADS 16
#define MTOT (BB * SS)   // 16384 rows

// Scratch (device globals; no allocation allowed)
__device__ float g_q[MTOT * HDIM];
__device__ float g_k[MTOT * HDIM];
__device__ float g_v[MTOT * HDIM];
__device__ float g_ctx[MTOT * HDIM];
__device__ float g_wosum[HDIM * DMODEL];

// ---------------------------------------------------------------------------
// Kernel 1: Wo_sum[d][n] = sum_h Wo[h*64+d][n]   (64 x 1024)
// ---------------------------------------------------------------------------
__global__ void wosum_kernel(const float* __restrict__ Wo) {
    int idx = blockIdx.x * blockDim.x + threadIdx.x;   // 0..65535
    int d = idx >> 10;           // / 1024
    int n = idx & (DMODEL - 1);  // % 1024
    float s = 0.f;
#pragma unroll
    for (int h = 0; h < NHEADS; h++)
        s += Wo[(h * HDIM + d) * DMODEL + n];
    g_wosum[idx] = s;
}

// ---------------------------------------------------------------------------
// Kernel 2: fused q/k/v projections.
// X[16384,1024] @ W[1024,64] + b -> out[16384,64]
// BM=128, BN=64, BK=16; 256 threads; 8x4 per thread.
// A stored transposed in smem -> a-reads are 2-address broadcasts per warp.
// ---------------------------------------------------------------------------
__global__ void proj_kernel(const float* __restrict__ Xq,
                            const float* __restrict__ Xk,
                            const float* __restrict__ Xv,
                            const float* __restrict__ Wq,
                            const float* __restrict__ Wk,
                            const float* __restrict__ Wv,
                            const float* __restrict__ bq,
                            const float* __restrict__ bk,
                            const float* __restrict__ bv) {
    const float* X; const float* W; const float* bias; float* out;
    if (blockIdx.y == 0)      { X = Xq; W = Wq; bias = bq; out = g_q; }
    else if (blockIdx.y == 1) { X = Xk; W = Wk; bias = bk; out = g_k; }
    else                      { X = Xv; W = Wv; bias = bv; out = g_v; }

    __shared__ float Ast[16][132];   // [BK][BM+pad] transposed A tile
    __shared__ float Bs[16][64];     // [BK][BN]

    const int tid = threadIdx.x;
    const int ty = tid >> 4;   // 0..15 -> 8 rows each
    const int tx = tid & 15;   // 0..15 -> 4 cols each
    const int row0 = blockIdx.x * 128;

    float acc[8][4];
#pragma unroll
    for (int i = 0; i < 8; i++)
#pragma unroll
        for (int j = 0; j < 4; j++) acc[i][j] = 0.f;

    for (int k0 = 0; k0 < DMODEL; k0 += 16) {
        // Load A tile (128x16) transposed into Ast[16][128]
#pragma unroll
        for (int it = 0; it < 8; it++) {
            int i = tid + it * 256;
            int r = i >> 4, c = i & 15;
            Ast[c][r] = X[(row0 + r) * DMODEL + k0 + c];
        }
        // Load B tile (16x64)
#pragma unroll
        for (int it = 0; it < 4; it++) {
            int i = tid + it * 256;
            int r = i >> 6, c = i & 63;
            Bs[r][c] = W[(k0 + r) * HDIM + c];
        }
        __syncthreads();

#pragma unroll
        for (int kk = 0; kk < 16; kk++) {
            float a[8], b[4];
#pragma unroll
            for (int i = 0; i < 8; i++) a[i] = Ast[kk][ty * 8 + i];
#pragma unroll
            for (int j = 0; j < 4; j++) b[j] = Bs[kk][tx * 4 + j];
#pragma unroll
            for (int i = 0; i < 8; i++)
#pragma unroll
                for (int j = 0; j < 4; j++)
                    acc[i][j] = fmaf(a[i], b[j], acc[i][j]);
        }
        __syncthreads();
    }

#pragma unroll
    for (int i = 0; i < 8; i++) {
        int r = row0 + ty * 8 + i;
#pragma unroll
        for (int j = 0; j < 4; j++) {
            int c = tx * 4 + j;
            out[r * HDIM + c] = acc[i][j] + bias[c];
        }
    }
}

// ---------------------------------------------------------------------------
// Kernel 3: flash attention (single logical head, head_dim 64).
// grid: (S/64, B); block 256; each block: 64 q-rows, loops 32 K/V tiles of 64.
// Dynamic smem: Qs/Ks/Vs/Ps each [64][65].
// ---------------------------------------------------------------------------
__global__ void attn_kernel() {
    extern __shared__ float sm[];
    float (*Qs)[65] = (float(*)[65])(sm);
    float (*Ks)[65] = (float(*)[65])(sm + 64 * 65);
    float (*Vs)[65] = (float(*)[65])(sm + 2 * 64 * 65);
    float (*Ps)[65] = (float(*)[65])(sm + 3 * 64 * 65);

    const int tid = threadIdx.x;
    const int ty = tid >> 4, tx = tid & 15;
    const int r0 = ty * 4, c0 = tx * 4;
    const int bq = blockIdx.x, bb = blockIdx.y;

    const float* Q = g_q + (bb * SS + bq * 64) * HDIM;
    const float* K = g_k + bb * SS * HDIM;
    const float* V = g_v + bb * SS * HDIM;

    // Load Q tile, scale folded in (1/sqrt(64) = 0.125)
#pragma unroll
    for (int it = 0; it < 16; it++) {
        int i = tid + it * 256;
        Qs[i >> 6][i & 63] = Q[i] * 0.125f;
    }

    float acc[4][4];
    float mrow[4], lrow[4];
#pragma unroll
    for (int i = 0; i < 4; i++) {
        mrow[i] = -1e30f; lrow[i] = 0.f;
#pragma unroll
        for (int j = 0; j < 4; j++) acc[i][j] = 0.f;
    }
    __syncthreads();

    for (int kt = 0; kt < SS / 64; kt++) {
        const float* Kt = K + kt * 64 * HDIM;
        const float* Vt = V + kt * 64 * HDIM;
#pragma unroll
        for (int it = 0; it < 16; it++) {
            int i = tid + it * 256;
            Ks[i >> 6][i & 63] = Kt[i];
            Vs[i >> 6][i & 63] = Vt[i];
        }
        __syncthreads();

        // S tile: s[i][j] = sum_d Qs[r0+i][d] * Ks[c0+j][d]
        float s[4][4];
#pragma unroll
        for (int i = 0; i < 4; i++)
#pragma unroll
            for (int j = 0; j < 4; j++) s[i][j] = 0.f;

#pragma unroll 8
        for (int d = 0; d < 64; d++) {
            float a[4], b[4];
#pragma unroll
            for (int i = 0; i < 4; i++) a[i] = Qs[r0 + i][d];
#pragma unroll
            for (int j = 0; j < 4; j++) b[j] = Ks[c0 + j][d];
#pragma unroll
            for (int i = 0; i < 4; i++)
#pragma unroll
                for (int j = 0; j < 4; j++)
                    s[i][j] = fmaf(a[i], b[j], s[i][j]);
        }

        // Online softmax per row (reduction across the 16 tx lanes)
#pragma unroll
        for (int i = 0; i < 4; i++) {
            float mt = s[i][0];
#pragma unroll
            for (int j = 1; j < 4; j++) mt = fmaxf(mt, s[i][j]);
#pragma unroll
            for (int off = 8; off > 0; off >>= 1)
                mt = fmaxf(mt, __shfl_xor_sync(0xffffffffu, mt, off));
            float mnew = fmaxf(mrow[i], mt);
            float corr = __expf(mrow[i] - mnew);
            float ls = 0.f;
#pragma unroll
            for (int j = 0; j < 4; j++) {
                s[i][j] = __expf(s[i][j] - mnew);
                ls += s[i][j];
            }
#pragma unroll
            for (int off = 8; off > 0; off >>= 1)
                ls += __shfl_xor_sync(0xffffffffu, ls, off);
            mrow[i] = mnew;
            lrow[i] = lrow[i] * corr + ls;
#pragma unroll
            for (int j = 0; j < 4; j++) acc[i][j] *= corr;
            Ps[r0 + i][c0 + 0] = s[i][0];
            Ps[r0 + i][c0 + 1] = s[i][1];
            Ps[r0 + i][c0 + 2] = s[i][2];
            Ps[r0 + i][c0 + 3] = s[i][3];
        }
        __syncthreads();

        // O update: acc[i][d] += sum_j Ps[r0+i][j] * Vs[j][c0+d]
#pragma unroll 8
        for (int j = 0; j < 64; j++) {
            float a[4], b[4];
#pragma unroll
            for (int i = 0; i < 4; i++) a[i] = Ps[r0 + i][j];
#pragma unroll
            for (int d = 0; d < 4; d++) b[d] = Vs[j][c0 + d];
#pragma unroll
            for (int i = 0; i < 4; i++)
#pragma unroll
                for (int d = 0; d < 4; d++)
                    acc[i][d] = fmaf(a[i], b[d], acc[i][d]);
        }
        __syncthreads();
    }

    float* O = g_ctx + (bb * SS + bq * 64) * HDIM;
#pragma unroll
    for (int i = 0; i < 4; i++) {
        float inv = 1.0f / lrow[i];
#pragma unroll
        for (int d = 0; d < 4; d++)
            O[(r0 + i) * HDIM + c0 + d] = acc[i][d] * inv;
    }
}

// ---------------------------------------------------------------------------
// Kernel 4: out = ctx[16384,64] @ Wo_sum[64,1024] + bo
// BM=64, BN=128, BK=64 (full K); 256 threads; 8x4 per thread.
// A-reads are full-warp broadcasts; B-reads are float4 (conflict-free phases).
// ---------------------------------------------------------------------------
__global__ void outproj_kernel(const float* __restrict__ bo,
                               float* __restrict__ out) {
    __shared__ float As[64][64];    // ctx tile (reads are broadcast; no pad needed)
    __shared__ float Bs[64][128];   // wosum tile (float4 reads)

    const int tid = threadIdx.x;
    const int ty = tid >> 5;   // 0..7  -> 8 rows each
    const int tx = tid & 31;   // 0..31 -> 4 cols each
    const int row0 = blockIdx.x * 64;
    const int n0 = blockIdx.y * 128;

#pragma unroll
    for (int it = 0; it < 16; it++) {
        int i = tid + it * 256;
        As[i >> 6][i & 63] = g_ctx[row0 * HDIM + i];
    }
#pragma unroll
    for (int it = 0; it < 32; it++) {
        int i = tid + it * 256;
        int k = i >> 7, n = i & 127;
        Bs[k][n] = g_wosum[k * DMODEL + n0 + n];
    }
    __syncthreads();

    float acc[8][4];
#pragma unroll
    for (int i = 0; i < 8; i++)
#pragma unroll
        for (int j = 0; j < 4; j++) acc[i][j] = 0.f;

#pragma unroll 8
    for (int k = 0; k < 64; k++) {
        float a[8];
#pragma unroll
        for (int i = 0; i < 8; i++) a[i] = As[ty * 8 + i][k];
        float4 b = *(const float4*)&Bs[k][tx * 4];
#pragma unroll
        for (int i = 0; i < 8; i++) {
            acc[i][0] = fmaf(a[i], b.x, acc[i][0]);
            acc[i][1] = fmaf(a[i], b.y, acc[i][1]);
            acc[i][2] = fmaf(a[i], b.z, acc[i][2]);
            acc[i][3] = fmaf(a[i], b.w, acc[i][3]);
        }
    }

    float4 bias = *(const float4*)&bo[n0 + tx * 4];
#pragma unroll
    for (int i = 0; i < 8; i++) {
        float4 o;
        o.x = acc[i][0] + bias.x;
        o.y = acc[i][1] + bias.y;
        o.z = acc[i][2] + bias.z;
        o.w = acc[i][3] + bias.w;
        *(float4*)&out[(row0 + ty * 8 + i) * DMODEL + n0 + tx * 4] = o;
    }
}

// ---------------------------------------------------------------------------
extern "C" void kernel_launch(void* const* d_in, const int* in_sizes, int n_in,
                              void* d_out, int out_size) {
    const float* query = (const float*)d_in[0];
    const float* key   = (const float*)d_in[1];
    const float* value = (const float*)d_in[2];
    const float* Wq    = (const float*)d_in[3];
    const float* bq    = (const float*)d_in[4];
    const float* Wk    = (const float*)d_in[5];
    const float* bk    = (const float*)d_in[6];
    const float* Wv    = (const float*)d_in[7];
    const float* bv    = (const float*)d_in[8];
    const float* Wo    = (const float*)d_in[9];
    const float* bo    = (const float*)d_in[10];
    float* out = (float*)d_out;

    // Attention kernel needs 66.5 KB dynamic smem (> 48 KB default).
    // Idempotent; called every launch (no static guards).
    cudaFuncSetAttribute(attn_kernel,
                         cudaFuncAttributeMaxDynamicSharedMemorySize,
                         4 * 64 * 65 * (int)sizeof(float));

    wosum_kernel<<<256, 256>>>(Wo);
    proj_kernel<<<dim3(128, 3), 256>>>(query, key, value,
                                       Wq, Wk, Wv, bq, bk, bv);
    attn_kernel<<<dim3(SS / 64, BB), 256, 4 * 64 * 65 * (int)sizeof(float)>>>();
    outproj_kernel<<<dim3(MTOT / 64, DMODEL / 128), 256>>>(bo, out);
}

// round 3
// speedup vs baseline: 1.6350x; 1.6350x over previous
#include <cuda_runtime.h>
#include <cuda_bf16.h>
#include <cstdint>

// Problem dims
#define BB 8
#define SS 2048
#define DMODEL 1024
#define HDIM 64
#define NHEADS 16
#define MTOT (BB * SS)   // 16384 tokens

// ---------------------------------------------------------------------------
// Scratch: everything stored as error-compensated bf16 pairs (hi + lo).
// q,k,ctx: [token][64] row-major.  v: TRANSPOSED [b][dim][s].  wo: [n][d].
// ---------------------------------------------------------------------------
__device__ __nv_bfloat16 g_qhi[MTOT * HDIM], g_qlo[MTOT * HDIM];
__device__ __nv_bfloat16 g_khi[MTOT * HDIM], g_klo[MTOT * HDIM];
__device__ __nv_bfloat16 g_vhi[MTOT * HDIM], g_vlo[MTOT * HDIM];   // [b][dim][s]
__device__ __nv_bfloat16 g_chi[MTOT * HDIM], g_clo[MTOT * HDIM];
__device__ __nv_bfloat16 g_wohi[DMODEL * HDIM], g_wolo[DMODEL * HDIM]; // [n][d]

// ---------------------------------------------------------------------------
// Helpers
// ---------------------------------------------------------------------------
__device__ __forceinline__ void mma_bf16(float c[4],
                                         uint32_t a0, uint32_t a1, uint32_t a2, uint32_t a3,
                                         uint32_t b0, uint32_t b1) {
    asm volatile(
        "mma.sync.aligned.m16n8k16.row.col.f32.bf16.bf16.f32 "
        "{%0,%1,%2,%3}, {%4,%5,%6,%7}, {%8,%9}, {%0,%1,%2,%3};\n"
        : "+f"(c[0]), "+f"(c[1]), "+f"(c[2]), "+f"(c[3])
        : "r"(a0), "r"(a1), "r"(a2), "r"(a3), "r"(b0), "r"(b1));
}

__device__ __forceinline__ void split1(float x, __nv_bfloat16& h, __nv_bfloat16& l) {
    h = __float2bfloat16(x);
    l = __float2bfloat16(x - __bfloat162float(h));
}

__device__ __forceinline__ void split_pack(float x, float y, uint32_t& hi, uint32_t& lo) {
    __nv_bfloat162 h, l;
    h.x = __float2bfloat16(x);
    h.y = __float2bfloat16(y);
    l.x = __float2bfloat16(x - __bfloat162float(h.x));
    l.y = __float2bfloat16(y - __bfloat162float(h.y));
    hi = *reinterpret_cast<uint32_t*>(&h);
    lo = *reinterpret_cast<uint32_t*>(&l);
}

// ---------------------------------------------------------------------------
// Kernel 1: Wo_sum^T[n][d] = sum_h Wo[h*64+d][n], split into bf16 hi/lo
// ---------------------------------------------------------------------------
__global__ void wosum_kernel(const float* __restrict__ Wo) {
    int idx = blockIdx.x * blockDim.x + threadIdx.x;   // 0..65535
    int d = idx >> 10;
    int n = idx & (DMODEL - 1);
    float s = 0.f;
#pragma unroll
    for (int h = 0; h < NHEADS; h++)
        s += Wo[(h * HDIM + d) * DMODEL + n];
    __nv_bfloat16 hi, lo;
    split1(s, hi, lo);
    g_wohi[n * HDIM + d] = hi;
    g_wolo[n * HDIM + d] = lo;
}

// ---------------------------------------------------------------------------
// Kernel 2: fused q/k/v projections via bf16x2-split tensor-core MMA.
// X[16384,1024] @ W[1024,64] + b.  BM=128, BN=64, BK=32. 256 thr, 8 warps
// (4 m-warps x 2 n-warps, warp tile 32x32). 3 MMAs per logical MMA.
// q scaled by 0.125; v written transposed [b][dim][s].
// ---------------------------------------------------------------------------
#define PP 40   // smem pitch (bf16) for BK=32 tiles -> conflict-free frags
__global__ __launch_bounds__(256) void proj_kernel(
    const float* __restrict__ Xq, const float* __restrict__ Xk, const float* __restrict__ Xv,
    const float* __restrict__ Wq, const float* __restrict__ Wk, const float* __restrict__ Wv,
    const float* __restrict__ bq, const float* __restrict__ bk, const float* __restrict__ bv) {

    const int which = blockIdx.y;
    const float* X;  const float* W;  const float* bias;
    if (which == 0)      { X = Xq; W = Wq; bias = bq; }
    else if (which == 1) { X = Xk; W = Wk; bias = bk; }
    else                 { X = Xv; W = Wv; bias = bv; }

    __shared__ __nv_bfloat16 Ash[128][PP], Asl[128][PP];
    __shared__ __nv_bfloat16 Bsh[64][PP],  Bsl[64][PP];   // W transposed: [n][k]

    const int tid  = threadIdx.x;
    const int warp = tid >> 5, lane = tid & 31;
    const int g = lane >> 2, tig = lane & 3;
    const int wm = warp & 3, wn = warp >> 2;
    const int row0 = blockIdx.x * 128;

    float c[2][4][4];
#pragma unroll
    for (int mt = 0; mt < 2; mt++)
#pragma unroll
        for (int nt = 0; nt < 4; nt++)
#pragma unroll
            for (int j = 0; j < 4; j++) c[mt][nt][j] = 0.f;

    for (int k0 = 0; k0 < DMODEL; k0 += 32) {
        // Stage X tile 128x32 (split to hi/lo)
#pragma unroll
        for (int it = 0; it < 4; it++) {
            int id = tid + it * 256;              // 0..1023 float4s
            int r = id >> 3, cg = (id & 7) * 4;
            float4 x4 = *(const float4*)(X + (row0 + r) * DMODEL + k0 + cg);
            __nv_bfloat16 h, l;
            split1(x4.x, h, l); Ash[r][cg + 0] = h; Asl[r][cg + 0] = l;
            split1(x4.y, h, l); Ash[r][cg + 1] = h; Asl[r][cg + 1] = l;
            split1(x4.z, h, l); Ash[r][cg + 2] = h; Asl[r][cg + 2] = l;
            split1(x4.w, h, l); Ash[r][cg + 3] = h; Asl[r][cg + 3] = l;
        }
        // Stage W tile 32x64 transposed into [n][k]
#pragma unroll
        for (int it = 0; it < 2; it++) {
            int id = tid + it * 256;              // 0..511 float4s
            int kr = id >> 4, cg = (id & 15) * 4;
            float4 w4 = *(const float4*)(W + (k0 + kr) * HDIM + cg);
            __nv_bfloat16 h, l;
            split1(w4.x, h, l); Bsh[cg + 0][kr] = h; Bsl[cg + 0][kr] = l;
            split1(w4.y, h, l); Bsh[cg + 1][kr] = h; Bsl[cg + 1][kr] = l;
            split1(w4.z, h, l); Bsh[cg + 2][kr] = h; Bsl[cg + 2][kr] = l;
            split1(w4.w, h, l); Bsh[cg + 3][kr] = h; Bsl[cg + 3][kr] = l;
        }
        __syncthreads();

#pragma unroll
        for (int kk = 0; kk < 2; kk++) {
            const int kb = kk * 16;
            uint32_t ah[2][4], al[2][4];
#pragma unroll
            for (int mt = 0; mt < 2; mt++) {
                int r = wm * 32 + mt * 16 + g;
                ah[mt][0] = *(const uint32_t*)&Ash[r    ][kb + 2 * tig];
                ah[mt][1] = *(const uint32_t*)&Ash[r + 8][kb + 2 * tig];
                ah[mt][2] = *(const uint32_t*)&Ash[r    ][kb + 8 + 2 * tig];
                ah[mt][3] = *(const uint32_t*)&Ash[r + 8][kb + 8 + 2 * tig];
                al[mt][0] = *(const uint32_t*)&Asl[r    ][kb + 2 * tig];
                al[mt][1] = *(const uint32_t*)&Asl[r + 8][kb + 2 * tig];
                al[mt][2] = *(const uint32_t*)&Asl[r    ][kb + 8 + 2 * tig];
                al[mt][3] = *(const uint32_t*)&Asl[r + 8][kb + 8 + 2 * tig];
            }
#pragma unroll
            for (int nt = 0; nt < 4; nt++) {
                int n = wn * 32 + nt * 8 + g;
                uint32_t bh0 = *(const uint32_t*)&Bsh[n][kb + 2 * tig];
                uint32_t bh1 = *(const uint32_t*)&Bsh[n][kb + 8 + 2 * tig];
                uint32_t bl0 = *(const uint32_t*)&Bsl[n][kb + 2 * tig];
                uint32_t bl1 = *(const uint32_t*)&Bsl[n][kb + 8 + 2 * tig];
#pragma unroll
                for (int mt = 0; mt < 2; mt++) {
                    mma_bf16(c[mt][nt], ah[mt][0], ah[mt][1], ah[mt][2], ah[mt][3], bh0, bh1);
                    mma_bf16(c[mt][nt], ah[mt][0], ah[mt][1], ah[mt][2], ah[mt][3], bl0, bl1);
                    mma_bf16(c[mt][nt], al[mt][0], al[mt][1], al[mt][2], al[mt][3], bh0, bh1);
                }
            }
        }
        __syncthreads();
    }

    // Epilogue: +bias, (x0.125 for q), split to hi/lo planes.
    const float scale = (which == 0) ? 0.125f : 1.0f;
    __nv_bfloat16* ohi = (which == 0) ? g_qhi : g_khi;
    __nv_bfloat16* olo = (which == 0) ? g_qlo : g_klo;

#pragma unroll
    for (int mt = 0; mt < 2; mt++) {
#pragma unroll
        for (int nt = 0; nt < 4; nt++) {
            int r   = row0 + wm * 32 + mt * 16 + g;
            int col = wn * 32 + nt * 8 + 2 * tig;
            float bv0 = bias[col], bv1 = bias[col + 1];
            float v0 = (c[mt][nt][0] + bv0) * scale;
            float v1 = (c[mt][nt][1] + bv1) * scale;
            float v2 = (c[mt][nt][2] + bv0) * scale;   // row r+8
            float v3 = (c[mt][nt][3] + bv1) * scale;
            if (which < 2) {
                uint32_t h, l;
                split_pack(v0, v1, h, l);
                *(uint32_t*)&ohi[r * HDIM + col] = h;
                *(uint32_t*)&olo[r * HDIM + col] = l;
                split_pack(v2, v3, h, l);
                *(uint32_t*)&ohi[(r + 8) * HDIM + col] = h;
                *(uint32_t*)&olo[(r + 8) * HDIM + col] = l;
            } else {
                // v transposed: [b][dim][s]
                int b = r >> 11, s = r & 2047;
                __nv_bfloat16 h, l;
                split1(v0, h, l);
                g_vhi[(b * HDIM + col) * SS + s] = h;     g_vlo[(b * HDIM + col) * SS + s] = l;
                split1(v1, h, l);
                g_vhi[(b * HDIM + col + 1) * SS + s] = h; g_vlo[(b * HDIM + col + 1) * SS + s] = l;
                split1(v2, h, l);
                g_vhi[(b * HDIM + col) * SS + s + 8] = h; g_vlo[(b * HDIM + col) * SS + s + 8] = l;
                split1(v3, h, l);
                g_vhi[(b * HDIM + col + 1) * SS + s + 8] = h;
                g_vlo[(b * HDIM + col + 1) * SS + s + 8] = l;
            }
        }
    }
}

// ---------------------------------------------------------------------------
// Kernel 3: flash attention with tensor cores.
// Block: 128 thr (4 warps), 64 q-rows (warp owns 16 rows, all 64 key-cols).
// Per key-tile (64 keys): S = QK^T (3-way split MMA), online softmax in
// accumulator registers, P fragments remapped in-register to A operands,
// ctx += P V (3-way split MMA, V staged pre-transposed).
// ---------------------------------------------------------------------------
#define AP 72   // smem pitch (bf16) for 64-wide tiles -> conflict-free frags
__global__ __launch_bounds__(128) void attn_kernel() {
    extern __shared__ __nv_bfloat16 sm[];
    __nv_bfloat16* Qh = sm;
    __nv_bfloat16* Ql = sm + 1 * 64 * AP;
    __nv_bfloat16* Kh = sm + 2 * 64 * AP;
    __nv_bfloat16* Kl = sm + 3 * 64 * AP;
    __nv_bfloat16* Vh = sm + 4 * 64 * AP;
    __nv_bfloat16* Vl = sm + 5 * 64 * AP;

    const int tid = threadIdx.x, warp = tid >> 5, lane = tid & 31;
    const int g = lane >> 2, tig = lane & 3;
    const int bq = blockIdx.x, b = blockIdx.y;
    const int t0 = b * SS + bq * 64;

    // Stage Q (once)
#pragma unroll
    for (int it = 0; it < 16; it++) {
        int id = tid + it * 128;                 // 0..2047 u32s
        int r = id >> 5, dp = (id & 31) * 2;
        *(uint32_t*)&Qh[r * AP + dp] = *(const uint32_t*)&g_qhi[(t0 + r) * HDIM + dp];
        *(uint32_t*)&Ql[r * AP + dp] = *(const uint32_t*)&g_qlo[(t0 + r) * HDIM + dp];
    }

    float m0 = -1e30f, m1 = -1e30f, l0 = 0.f, l1 = 0.f;
    float o[8][4];
#pragma unroll
    for (int nt = 0; nt < 8; nt++)
#pragma unroll
        for (int j = 0; j < 4; j++) o[nt][j] = 0.f;

    const __nv_bfloat16* kbh = g_khi + (size_t)b * SS * HDIM;
    const __nv_bfloat16* kbl = g_klo + (size_t)b * SS * HDIM;
    const __nv_bfloat16* vbh = g_vhi + (size_t)b * HDIM * SS;
    const __nv_bfloat16* vbl = g_vlo + (size_t)b * HDIM * SS;

    for (int kt = 0; kt < SS / 64; kt++) {
        // Stage K (row-major) and V (already [dim][s] -> rows=dim)
#pragma unroll
        for (int it = 0; it < 16; it++) {
            int id = tid + it * 128;
            int r = id >> 5, dp = (id & 31) * 2;
            *(uint32_t*)&Kh[r * AP + dp] = *(const uint32_t*)&kbh[(kt * 64 + r) * HDIM + dp];
            *(uint32_t*)&Kl[r * AP + dp] = *(const uint32_t*)&kbl[(kt * 64 + r) * HDIM + dp];
            *(uint32_t*)&Vh[r * AP + dp] = *(const uint32_t*)&vbh[r * SS + kt * 64 + dp];
            *(uint32_t*)&Vl[r * AP + dp] = *(const uint32_t*)&vbl[r * SS + kt * 64 + dp];
        }
        __syncthreads();

        // S = Q K^T
        float s[8][4];
#pragma unroll
        for (int nt = 0; nt < 8; nt++)
#pragma unroll
            for (int j = 0; j < 4; j++) s[nt][j] = 0.f;

#pragma unroll
        for (int kc = 0; kc < 4; kc++) {
            const int kb = kc * 16;
            const int r = warp * 16 + g;
            uint32_t qh0 = *(const uint32_t*)&Qh[r * AP + kb + 2 * tig];
            uint32_t qh1 = *(const uint32_t*)&Qh[(r + 8) * AP + kb + 2 * tig];
            uint32_t qh2 = *(const uint32_t*)&Qh[r * AP + kb + 8 + 2 * tig];
            uint32_t qh3 = *(const uint32_t*)&Qh[(r + 8) * AP + kb + 8 + 2 * tig];
            uint32_t ql0 = *(const uint32_t*)&Ql[r * AP + kb + 2 * tig];
            uint32_t ql1 = *(const uint32_t*)&Ql[(r + 8) * AP + kb + 2 * tig];
            uint32_t ql2 = *(const uint32_t*)&Ql[r * AP + kb + 8 + 2 * tig];
            uint32_t ql3 = *(const uint32_t*)&Ql[(r + 8) * AP + kb + 8 + 2 * tig];
#pragma unroll
            for (int nt = 0; nt < 8; nt++) {
                int n = nt * 8 + g;
                uint32_t kh0 = *(const uint32_t*)&Kh[n * AP + kb + 2 * tig];
                uint32_t kh1 = *(const uint32_t*)&Kh[n * AP + kb + 8 + 2 * tig];
                uint32_t kl0 = *(const uint32_t*)&Kl[n * AP + kb + 2 * tig];
                uint32_t kl1 = *(const uint32_t*)&Kl[n * AP + kb + 8 + 2 * tig];
                mma_bf16(s[nt], qh0, qh1, qh2, qh3, kh0, kh1);
                mma_bf16(s[nt], qh0, qh1, qh2, qh3, kl0, kl1);
                mma_bf16(s[nt], ql0, ql1, ql2, ql3, kh0, kh1);
            }
        }

        // Online softmax. Row r (regs 0,1), row r+8 (regs 2,3); reduce over tig.
        float mt0 = -1e30f, mt1 = -1e30f;
#pragma unroll
        for (int nt = 0; nt < 8; nt++) {
            mt0 = fmaxf(mt0, fmaxf(s[nt][0], s[nt][1]));
            mt1 = fmaxf(mt1, fmaxf(s[nt][2], s[nt][3]));
        }
        mt0 = fmaxf(mt0, __shfl_xor_sync(0xffffffffu, mt0, 1));
        mt0 = fmaxf(mt0, __shfl_xor_sync(0xffffffffu, mt0, 2));
        mt1 = fmaxf(mt1, __shfl_xor_sync(0xffffffffu, mt1, 1));
        mt1 = fmaxf(mt1, __shfl_xor_sync(0xffffffffu, mt1, 2));
        float mn0 = fmaxf(m0, mt0), mn1 = fmaxf(m1, mt1);
        float cr0 = __expf(m0 - mn0), cr1 = __expf(m1 - mn1);
        m0 = mn0; m1 = mn1;
        float ls0 = 0.f, ls1 = 0.f;
#pragma unroll
        for (int nt = 0; nt < 8; nt++) {
            s[nt][0] = __expf(s[nt][0] - mn0); ls0 += s[nt][0];
            s[nt][1] = __expf(s[nt][1] - mn0); ls0 += s[nt][1];
            s[nt][2] = __expf(s[nt][2] - mn1); ls1 += s[nt][2];
            s[nt][3] = __expf(s[nt][3] - mn1); ls1 += s[nt][3];
        }
        ls0 += __shfl_xor_sync(0xffffffffu, ls0, 1);
        ls0 += __shfl_xor_sync(0xffffffffu, ls0, 2);
        ls1 += __shfl_xor_sync(0xffffffffu, ls1, 1);
        ls1 += __shfl_xor_sync(0xffffffffu, ls1, 2);
        l0 = l0 * cr0 + ls0;
        l1 = l1 * cr1 + ls1;
#pragma unroll
        for (int nt = 0; nt < 8; nt++) {
            o[nt][0] *= cr0; o[nt][1] *= cr0;
            o[nt][2] *= cr1; o[nt][3] *= cr1;
        }

        // ctx += P V  (P fragments straight from accumulators)
#pragma unroll
        for (int kc = 0; kc < 4; kc++) {
            const int kb = kc * 16;
            uint32_t ph0, pl0, ph1, pl1, ph2, pl2, ph3, pl3;
            split_pack(s[2 * kc][0],     s[2 * kc][1],     ph0, pl0);
            split_pack(s[2 * kc][2],     s[2 * kc][3],     ph1, pl1);
            split_pack(s[2 * kc + 1][0], s[2 * kc + 1][1], ph2, pl2);
            split_pack(s[2 * kc + 1][2], s[2 * kc + 1][3], ph3, pl3);
#pragma unroll
            for (int nt = 0; nt < 8; nt++) {
                int n = nt * 8 + g;
                uint32_t vh0 = *(const uint32_t*)&Vh[n * AP + kb + 2 * tig];
                uint32_t vh1 = *(const uint32_t*)&Vh[n * AP + kb + 8 + 2 * tig];
                uint32_t vl0 = *(const uint32_t*)&Vl[n * AP + kb + 2 * tig];
                uint32_t vl1 = *(const uint32_t*)&Vl[n * AP + kb + 8 + 2 * tig];
                mma_bf16(o[nt], ph0, ph1, ph2, ph3, vh0, vh1);
                mma_bf16(o[nt], ph0, ph1, ph2, ph3, vl0, vl1);
                mma_bf16(o[nt], pl0, pl1, pl2, pl3, vh0, vh1);
            }
        }
        __syncthreads();
    }

    // Normalize + store ctx hi/lo
    float inv0 = 1.0f / l0, inv1 = 1.0f / l1;
#pragma unroll
    for (int nt = 0; nt < 8; nt++) {
        int r   = t0 + warp * 16 + g;
        int col = nt * 8 + 2 * tig;
        uint32_t h, l;
        split_pack(o[nt][0] * inv0, o[nt][1] * inv0, h, l);
        *(uint32_t*)&g_chi[r * HDIM + col] = h;
        *(uint32_t*)&g_clo[r * HDIM + col] = l;
        split_pack(o[nt][2] * inv1, o[nt][3] * inv1, h, l);
        *(uint32_t*)&g_chi[(r + 8) * HDIM + col] = h;
        *(uint32_t*)&g_clo[(r + 8) * HDIM + col] = l;
    }
}

// ---------------------------------------------------------------------------
// Kernel 4: out = ctx[16384,64] @ Wo_sum[64,1024] + bo, split tensor-core MMA.
// BM=128, BN=64, K=64. 256 thr, 8 warps (4x2), warp tile 32x32.
// ---------------------------------------------------------------------------
__global__ __launch_bounds__(256) void outproj_kernel(const float* __restrict__ bo,
                                                      float* __restrict__ out) {
    extern __shared__ __nv_bfloat16 sm[];
    __nv_bfloat16* Ash = sm;                       // ctx hi [128][AP]
    __nv_bfloat16* Asl = sm + 128 * AP;
    __nv_bfloat16* Bsh = sm + 2 * 128 * AP;        // woT hi [64][AP]
    __nv_bfloat16* Bsl = Bsh + 64 * AP;

    const int tid = threadIdx.x, warp = tid >> 5, lane = tid & 31;
    const int g = lane >> 2, tig = lane & 3;
    const int wm = warp & 3, wn = warp >> 2;
    const int row0 = blockIdx.x * 128, n0 = blockIdx.y * 64;

#pragma unroll
    for (int it = 0; it < 16; it++) {
        int id = tid + it * 256;                  // 0..4095 u32s
        int r = id >> 5, dp = (id & 31) * 2;
        *(uint32_t*)&Ash[r * AP + dp] = *(const uint32_t*)&g_chi[(row0 + r) * HDIM + dp];
        *(uint32_t*)&Asl[r * AP + dp] = *(const uint32_t*)&g_clo[(row0 + r) * HDIM + dp];
    }
#pragma unroll
    for (int it = 0; it < 8; it++) {
        int id = tid + it * 256;                  // 0..2047 u32s
        int n = id >> 5, dp = (id & 31) * 2;
        *(uint32_t*)&Bsh[n * AP + dp] = *(const uint32_t*)&g_wohi[(n0 + n) * HDIM + dp];
        *(uint32_t*)&Bsl[n * AP + dp] = *(const uint32_t*)&g_wolo[(n0 + n) * HDIM + dp];
    }
    __syncthreads();

    float c[2][4][4];
#pragma unroll
    for (int mt = 0; mt < 2; mt++)
#pragma unroll
        for (int nt = 0; nt < 4; nt++)
#pragma unroll
            for (int j = 0; j < 4; j++) c[mt][nt][j] = 0.f;

#pragma unroll
    for (int kc = 0; kc < 4; kc++) {
        const int kb = kc * 16;
        uint32_t ah[2][4], al[2][4];
#pragma unroll
        for (int mt = 0; mt < 2; mt++) {
            int r = wm * 32 + mt * 16 + g;
            ah[mt][0] = *(const uint32_t*)&Ash[r * AP + kb + 2 * tig];
            ah[mt][1] = *(const uint32_t*)&Ash[(r + 8) * AP + kb + 2 * tig];
            ah[mt][2] = *(const uint32_t*)&Ash[r * AP + kb + 8 + 2 * tig];
            ah[mt][3] = *(const uint32_t*)&Ash[(r + 8) * AP + kb + 8 + 2 * tig];
            al[mt][0] = *(const uint32_t*)&Asl[r * AP + kb + 2 * tig];
            al[mt][1] = *(const uint32_t*)&Asl[(r + 8) * AP + kb + 2 * tig];
            al[mt][2] = *(const uint32_t*)&Asl[r * AP + kb + 8 + 2 * tig];
            al[mt][3] = *(const uint32_t*)&Asl[(r + 8) * AP + kb + 8 + 2 * tig];
        }
#pragma unroll
        for (int nt = 0; nt < 4; nt++) {
            int n = wn * 32 + nt * 8 + g;
            uint32_t bh0 = *(const uint32_t*)&Bsh[n * AP + kb + 2 * tig];
            uint32_t bh1 = *(const uint32_t*)&Bsh[n * AP + kb + 8 + 2 * tig];
            uint32_t bl0 = *(const uint32_t*)&Bsl[n * AP + kb + 2 * tig];
            uint32_t bl1 = *(const uint32_t*)&Bsl[n * AP + kb + 8 + 2 * tig];
#pragma unroll
            for (int mt = 0; mt < 2; mt++) {
                mma_bf16(c[mt][nt], ah[mt][0], ah[mt][1], ah[mt][2], ah[mt][3], bh0, bh1);
                mma_bf16(c[mt][nt], ah[mt][0], ah[mt][1], ah[mt][2], ah[mt][3], bl0, bl1);
                mma_bf16(c[mt][nt], al[mt][0], al[mt][1], al[mt][2], al[mt][3], bh0, bh1);
            }
        }
    }

#pragma unroll
    for (int mt = 0; mt < 2; mt++) {
#pragma unroll
        for (int nt = 0; nt < 4; nt++) {
            int r   = row0 + wm * 32 + mt * 16 + g;
            int col = n0 + wn * 32 + nt * 8 + 2 * tig;
            float bv0 = bo[col], bv1 = bo[col + 1];
            float2 v0 = make_float2(c[mt][nt][0] + bv0, c[mt][nt][1] + bv1);
            float2 v1 = make_float2(c[mt][nt][2] + bv0, c[mt][nt][3] + bv1);
            *(float2*)&out[r * DMODEL + col] = v0;
            *(float2*)&out[(r + 8) * DMODEL + col] = v1;
        }
    }
}

// ---------------------------------------------------------------------------
extern "C" void kernel_launch(void* const* d_in, const int* in_sizes, int n_in,
                              void* d_out, int out_size) {
    const float* query = (const float*)d_in[0];
    const float* key   = (const float*)d_in[1];
    const float* value = (const float*)d_in[2];
    const float* Wq    = (const float*)d_in[3];
    const float* bq    = (const float*)d_in[4];
    const float* Wk    = (const float*)d_in[5];
    const float* bk    = (const float*)d_in[6];
    const float* Wv    = (const float*)d_in[7];
    const float* bv    = (const float*)d_in[8];
    const float* Wo    = (const float*)d_in[9];
    const float* bo    = (const float*)d_in[10];
    float* out = (float*)d_out;

    const int ATTN_SMEM = 6 * 64 * AP * (int)sizeof(__nv_bfloat16);   // 55296
    const int OUTP_SMEM = (2 * 128 + 2 * 64) * AP * (int)sizeof(__nv_bfloat16); // 55296
    cudaFuncSetAttribute(attn_kernel, cudaFuncAttributeMaxDynamicSharedMemorySize, ATTN_SMEM);
    cudaFuncSetAttribute(outproj_kernel, cudaFuncAttributeMaxDynamicSharedMemorySize, OUTP_SMEM);

    wosum_kernel<<<256, 256>>>(Wo);
    proj_kernel<<<dim3(128, 3), 256>>>(query, key, value,
                                       Wq, Wk, Wv, bq, bk, bv);
    attn_kernel<<<dim3(SS / 64, BB), 128, ATTN_SMEM>>>();
    outproj_kernel<<<dim3(MTOT / 128, DMODEL / 64), 256, OUTP_SMEM>>>(bo, out);
}

// round 4
// speedup vs baseline: 1.7279x; 1.0568x over previous
#include <cuda_runtime.h>
#include <cuda_bf16.h>
#include <cstdint>

// Problem dims
#define BB 8
#define SS 2048
#define DMODEL 1024
#define HDIM 64
#define NHEADS 16
#define MTOT (BB * SS)   // 16384 tokens
#define NSPLIT 4         // KV splits
#define KPS (SS / NSPLIT) // 512 keys per split

// ---------------------------------------------------------------------------
// Scratch: error-compensated bf16 pairs (hi + lo).
// q,k,ctx: [token][64] row-major.  v: TRANSPOSED [b][dim][s].  wo: [n][d].
// ---------------------------------------------------------------------------
__device__ __nv_bfloat16 g_qhi[MTOT * HDIM], g_qlo[MTOT * HDIM];
__device__ __nv_bfloat16 g_khi[MTOT * HDIM], g_klo[MTOT * HDIM];
__device__ __nv_bfloat16 g_vhi[MTOT * HDIM], g_vlo[MTOT * HDIM];   // [b][dim][s]
__device__ __nv_bfloat16 g_chi[MTOT * HDIM], g_clo[MTOT * HDIM];
__device__ __nv_bfloat16 g_wohi[DMODEL * HDIM], g_wolo[DMODEL * HDIM]; // [n][d]
// Split-KV partials (fp32, unnormalized o; m,l in log2 domain)
__device__ float g_po[NSPLIT * MTOT * HDIM];
__device__ float g_pm[NSPLIT * MTOT];
__device__ float g_pl[NSPLIT * MTOT];

// ---------------------------------------------------------------------------
// Helpers
// ---------------------------------------------------------------------------
__device__ __forceinline__ void mma_bf16(float c[4],
                                         uint32_t a0, uint32_t a1, uint32_t a2, uint32_t a3,
                                         uint32_t b0, uint32_t b1) {
    asm volatile(
        "mma.sync.aligned.m16n8k16.row.col.f32.bf16.bf16.f32 "
        "{%0,%1,%2,%3}, {%4,%5,%6,%7}, {%8,%9}, {%0,%1,%2,%3};\n"
        : "+f"(c[0]), "+f"(c[1]), "+f"(c[2]), "+f"(c[3])
        : "r"(a0), "r"(a1), "r"(a2), "r"(a3), "r"(b0), "r"(b1));
}

__device__ __forceinline__ void split1(float x, __nv_bfloat16& h, __nv_bfloat16& l) {
    h = __float2bfloat16(x);
    l = __float2bfloat16(x - __bfloat162float(h));
}

__device__ __forceinline__ void split_pack(float x, float y, uint32_t& hi, uint32_t& lo) {
    __nv_bfloat162 h, l;
    h.x = __float2bfloat16(x);
    h.y = __float2bfloat16(y);
    l.x = __float2bfloat16(x - __bfloat162float(h.x));
    l.y = __float2bfloat16(y - __bfloat162float(h.y));
    hi = *reinterpret_cast<uint32_t*>(&h);
    lo = *reinterpret_cast<uint32_t*>(&l);
}

// ---------------------------------------------------------------------------
// Kernel 1: Wo_sum^T[n][d] = sum_h Wo[h*64+d][n], split into bf16 hi/lo
// ---------------------------------------------------------------------------
__global__ void wosum_kernel(const float* __restrict__ Wo) {
    int idx = blockIdx.x * blockDim.x + threadIdx.x;   // 0..65535
    int d = idx >> 10;
    int n = idx & (DMODEL - 1);
    float s = 0.f;
#pragma unroll
    for (int h = 0; h < NHEADS; h++)
        s += Wo[(h * HDIM + d) * DMODEL + n];
    __nv_bfloat16 hi, lo;
    split1(s, hi, lo);
    g_wohi[n * HDIM + d] = hi;
    g_wolo[n * HDIM + d] = lo;
}

// ---------------------------------------------------------------------------
// Kernel 2: fused q/k/v projections via bf16x2-split tensor-core MMA.
// X[16384,1024] @ W[1024,64] + b.  BM=128, BN=64, BK=32. 256 thr, 8 warps.
// q scaled by 0.125*log2(e) (softmax runs in base-2); v written [b][dim][s].
// ---------------------------------------------------------------------------
#define PP 40   // smem pitch (bf16)
#define QSCALE (0.125f * 1.4426950408889634f)
__global__ __launch_bounds__(256) void proj_kernel(
    const float* __restrict__ Xq, const float* __restrict__ Xk, const float* __restrict__ Xv,
    const float* __restrict__ Wq, const float* __restrict__ Wk, const float* __restrict__ Wv,
    const float* __restrict__ bq, const float* __restrict__ bk, const float* __restrict__ bv) {

    const int which = blockIdx.y;
    const float* X;  const float* W;  const float* bias;
    if (which == 0)      { X = Xq; W = Wq; bias = bq; }
    else if (which == 1) { X = Xk; W = Wk; bias = bk; }
    else                 { X = Xv; W = Wv; bias = bv; }

    __shared__ __nv_bfloat16 Ash[128][PP], Asl[128][PP];
    __shared__ __nv_bfloat16 Bsh[64][PP],  Bsl[64][PP];   // W transposed: [n][k]

    const int tid  = threadIdx.x;
    const int warp = tid >> 5, lane = tid & 31;
    const int g = lane >> 2, tig = lane & 3;
    const int wm = warp & 3, wn = warp >> 2;
    const int row0 = blockIdx.x * 128;

    float c[2][4][4];
#pragma unroll
    for (int mt = 0; mt < 2; mt++)
#pragma unroll
        for (int nt = 0; nt < 4; nt++)
#pragma unroll
            for (int j = 0; j < 4; j++) c[mt][nt][j] = 0.f;

    for (int k0 = 0; k0 < DMODEL; k0 += 32) {
#pragma unroll
        for (int it = 0; it < 4; it++) {
            int id = tid + it * 256;
            int r = id >> 3, cg = (id & 7) * 4;
            float4 x4 = *(const float4*)(X + (row0 + r) * DMODEL + k0 + cg);
            __nv_bfloat16 h, l;
            split1(x4.x, h, l); Ash[r][cg + 0] = h; Asl[r][cg + 0] = l;
            split1(x4.y, h, l); Ash[r][cg + 1] = h; Asl[r][cg + 1] = l;
            split1(x4.z, h, l); Ash[r][cg + 2] = h; Asl[r][cg + 2] = l;
            split1(x4.w, h, l); Ash[r][cg + 3] = h; Asl[r][cg + 3] = l;
        }
#pragma unroll
        for (int it = 0; it < 2; it++) {
            int id = tid + it * 256;
            int kr = id >> 4, cg = (id & 15) * 4;
            float4 w4 = *(const float4*)(W + (k0 + kr) * HDIM + cg);
            __nv_bfloat16 h, l;
            split1(w4.x, h, l); Bsh[cg + 0][kr] = h; Bsl[cg + 0][kr] = l;
            split1(w4.y, h, l); Bsh[cg + 1][kr] = h; Bsl[cg + 1][kr] = l;
            split1(w4.z, h, l); Bsh[cg + 2][kr] = h; Bsl[cg + 2][kr] = l;
            split1(w4.w, h, l); Bsh[cg + 3][kr] = h; Bsl[cg + 3][kr] = l;
        }
        __syncthreads();

#pragma unroll
        for (int kk = 0; kk < 2; kk++) {
            const int kb = kk * 16;
            uint32_t ah[2][4], al[2][4];
#pragma unroll
            for (int mt = 0; mt < 2; mt++) {
                int r = wm * 32 + mt * 16 + g;
                ah[mt][0] = *(const uint32_t*)&Ash[r    ][kb + 2 * tig];
                ah[mt][1] = *(const uint32_t*)&Ash[r + 8][kb + 2 * tig];
                ah[mt][2] = *(const uint32_t*)&Ash[r    ][kb + 8 + 2 * tig];
                ah[mt][3] = *(const uint32_t*)&Ash[r + 8][kb + 8 + 2 * tig];
                al[mt][0] = *(const uint32_t*)&Asl[r    ][kb + 2 * tig];
                al[mt][1] = *(const uint32_t*)&Asl[r + 8][kb + 2 * tig];
                al[mt][2] = *(const uint32_t*)&Asl[r    ][kb + 8 + 2 * tig];
                al[mt][3] = *(const uint32_t*)&Asl[r + 8][kb + 8 + 2 * tig];
            }
#pragma unroll
            for (int nt = 0; nt < 4; nt++) {
                int n = wn * 32 + nt * 8 + g;
                uint32_t bh0 = *(const uint32_t*)&Bsh[n][kb + 2 * tig];
                uint32_t bh1 = *(const uint32_t*)&Bsh[n][kb + 8 + 2 * tig];
                uint32_t bl0 = *(const uint32_t*)&Bsl[n][kb + 2 * tig];
                uint32_t bl1 = *(const uint32_t*)&Bsl[n][kb + 8 + 2 * tig];
#pragma unroll
                for (int mt = 0; mt < 2; mt++) {
                    mma_bf16(c[mt][nt], ah[mt][0], ah[mt][1], ah[mt][2], ah[mt][3], bh0, bh1);
                    mma_bf16(c[mt][nt], ah[mt][0], ah[mt][1], ah[mt][2], ah[mt][3], bl0, bl1);
                    mma_bf16(c[mt][nt], al[mt][0], al[mt][1], al[mt][2], al[mt][3], bh0, bh1);
                }
            }
        }
        __syncthreads();
    }

    const float scale = (which == 0) ? QSCALE : 1.0f;
    __nv_bfloat16* ohi = (which == 0) ? g_qhi : g_khi;
    __nv_bfloat16* olo = (which == 0) ? g_qlo : g_klo;

#pragma unroll
    for (int mt = 0; mt < 2; mt++) {
#pragma unroll
        for (int nt = 0; nt < 4; nt++) {
            int r   = row0 + wm * 32 + mt * 16 + g;
            int col = wn * 32 + nt * 8 + 2 * tig;
            float bv0 = bias[col], bv1 = bias[col + 1];
            float v0 = (c[mt][nt][0] + bv0) * scale;
            float v1 = (c[mt][nt][1] + bv1) * scale;
            float v2 = (c[mt][nt][2] + bv0) * scale;
            float v3 = (c[mt][nt][3] + bv1) * scale;
            if (which < 2) {
                uint32_t h, l;
                split_pack(v0, v1, h, l);
                *(uint32_t*)&ohi[r * HDIM + col] = h;
                *(uint32_t*)&olo[r * HDIM + col] = l;
                split_pack(v2, v3, h, l);
                *(uint32_t*)&ohi[(r + 8) * HDIM + col] = h;
                *(uint32_t*)&olo[(r + 8) * HDIM + col] = l;
            } else {
                int b = r >> 11, s = r & 2047;
                __nv_bfloat16 h, l;
                split1(v0, h, l);
                g_vhi[(b * HDIM + col) * SS + s] = h;     g_vlo[(b * HDIM + col) * SS + s] = l;
                split1(v1, h, l);
                g_vhi[(b * HDIM + col + 1) * SS + s] = h; g_vlo[(b * HDIM + col + 1) * SS + s] = l;
                split1(v2, h, l);
                g_vhi[(b * HDIM + col) * SS + s + 8] = h; g_vlo[(b * HDIM + col) * SS + s + 8] = l;
                split1(v3, h, l);
                g_vhi[(b * HDIM + col + 1) * SS + s + 8] = h;
                g_vlo[(b * HDIM + col + 1) * SS + s + 8] = l;
            }
        }
    }
}

// ---------------------------------------------------------------------------
// Kernel 3: split-KV flash attention with tensor cores.
// grid (S/64, B, NSPLIT); block 128 (4 warps, warp owns 16 q-rows).
// Each block: 64 q-rows x 512 keys; writes unnormalized partial (o, m, l).
// Softmax in base-2 (scores pre-scaled by log2 e) -> pure exp2f.
// ---------------------------------------------------------------------------
#define AP 72   // smem pitch (bf16)
__global__ __launch_bounds__(128) void attn_kernel() {
    extern __shared__ __nv_bfloat16 sm[];
    __nv_bfloat16* Qh = sm;
    __nv_bfloat16* Ql = sm + 1 * 64 * AP;
    __nv_bfloat16* Kh = sm + 2 * 64 * AP;
    __nv_bfloat16* Kl = sm + 3 * 64 * AP;
    __nv_bfloat16* Vh = sm + 4 * 64 * AP;
    __nv_bfloat16* Vl = sm + 5 * 64 * AP;

    const int tid = threadIdx.x, warp = tid >> 5, lane = tid & 31;
    const int g = lane >> 2, tig = lane & 3;
    const int bq = blockIdx.x, b = blockIdx.y, split = blockIdx.z;
    const int t0 = b * SS + bq * 64;
    const int kt0 = split * (KPS / 64);

#pragma unroll
    for (int it = 0; it < 16; it++) {
        int id = tid + it * 128;
        int r = id >> 5, dp = (id & 31) * 2;
        *(uint32_t*)&Qh[r * AP + dp] = *(const uint32_t*)&g_qhi[(t0 + r) * HDIM + dp];
        *(uint32_t*)&Ql[r * AP + dp] = *(const uint32_t*)&g_qlo[(t0 + r) * HDIM + dp];
    }

    float m0 = -1e30f, m1 = -1e30f, l0 = 0.f, l1 = 0.f;
    float o[8][4];
#pragma unroll
    for (int nt = 0; nt < 8; nt++)
#pragma unroll
        for (int j = 0; j < 4; j++) o[nt][j] = 0.f;

    const __nv_bfloat16* kbh = g_khi + (size_t)b * SS * HDIM;
    const __nv_bfloat16* kbl = g_klo + (size_t)b * SS * HDIM;
    const __nv_bfloat16* vbh = g_vhi + (size_t)b * HDIM * SS;
    const __nv_bfloat16* vbl = g_vlo + (size_t)b * HDIM * SS;

    for (int kt = kt0; kt < kt0 + KPS / 64; kt++) {
#pragma unroll
        for (int it = 0; it < 16; it++) {
            int id = tid + it * 128;
            int r = id >> 5, dp = (id & 31) * 2;
            *(uint32_t*)&Kh[r * AP + dp] = *(const uint32_t*)&kbh[(kt * 64 + r) * HDIM + dp];
            *(uint32_t*)&Kl[r * AP + dp] = *(const uint32_t*)&kbl[(kt * 64 + r) * HDIM + dp];
            *(uint32_t*)&Vh[r * AP + dp] = *(const uint32_t*)&vbh[r * SS + kt * 64 + dp];
            *(uint32_t*)&Vl[r * AP + dp] = *(const uint32_t*)&vbl[r * SS + kt * 64 + dp];
        }
        __syncthreads();

        float s[8][4];
#pragma unroll
        for (int nt = 0; nt < 8; nt++)
#pragma unroll
            for (int j = 0; j < 4; j++) s[nt][j] = 0.f;

#pragma unroll
        for (int kc = 0; kc < 4; kc++) {
            const int kb = kc * 16;
            const int r = warp * 16 + g;
            uint32_t qh0 = *(const uint32_t*)&Qh[r * AP + kb + 2 * tig];
            uint32_t qh1 = *(const uint32_t*)&Qh[(r + 8) * AP + kb + 2 * tig];
            uint32_t qh2 = *(const uint32_t*)&Qh[r * AP + kb + 8 + 2 * tig];
            uint32_t qh3 = *(const uint32_t*)&Qh[(r + 8) * AP + kb + 8 + 2 * tig];
            uint32_t ql0 = *(const uint32_t*)&Ql[r * AP + kb + 2 * tig];
            uint32_t ql1 = *(const uint32_t*)&Ql[(r + 8) * AP + kb + 2 * tig];
            uint32_t ql2 = *(const uint32_t*)&Ql[r * AP + kb + 8 + 2 * tig];
            uint32_t ql3 = *(const uint32_t*)&Ql[(r + 8) * AP + kb + 8 + 2 * tig];
#pragma unroll
            for (int nt = 0; nt < 8; nt++) {
                int n = nt * 8 + g;
                uint32_t kh0 = *(const uint32_t*)&Kh[n * AP + kb + 2 * tig];
                uint32_t kh1 = *(const uint32_t*)&Kh[n * AP + kb + 8 + 2 * tig];
                uint32_t kl0 = *(const uint32_t*)&Kl[n * AP + kb + 2 * tig];
                uint32_t kl1 = *(const uint32_t*)&Kl[n * AP + kb + 8 + 2 * tig];
                mma_bf16(s[nt], qh0, qh1, qh2, qh3, kh0, kh1);
                mma_bf16(s[nt], qh0, qh1, qh2, qh3, kl0, kl1);
                mma_bf16(s[nt], ql0, ql1, ql2, ql3, kh0, kh1);
            }
        }

        // Online softmax, base-2 domain
        float mt0 = -1e30f, mt1 = -1e30f;
#pragma unroll
        for (int nt = 0; nt < 8; nt++) {
            mt0 = fmaxf(mt0, fmaxf(s[nt][0], s[nt][1]));
            mt1 = fmaxf(mt1, fmaxf(s[nt][2], s[nt][3]));
        }
        mt0 = fmaxf(mt0, __shfl_xor_sync(0xffffffffu, mt0, 1));
        mt0 = fmaxf(mt0, __shfl_xor_sync(0xffffffffu, mt0, 2));
        mt1 = fmaxf(mt1, __shfl_xor_sync(0xffffffffu, mt1, 1));
        mt1 = fmaxf(mt1, __shfl_xor_sync(0xffffffffu, mt1, 2));
        float mn0 = fmaxf(m0, mt0), mn1 = fmaxf(m1, mt1);
        float cr0 = exp2f(m0 - mn0), cr1 = exp2f(m1 - mn1);
        m0 = mn0; m1 = mn1;
        float ls0 = 0.f, ls1 = 0.f;
#pragma unroll
        for (int nt = 0; nt < 8; nt++) {
            s[nt][0] = exp2f(s[nt][0] - mn0); ls0 += s[nt][0];
            s[nt][1] = exp2f(s[nt][1] - mn0); ls0 += s[nt][1];
            s[nt][2] = exp2f(s[nt][2] - mn1); ls1 += s[nt][2];
            s[nt][3] = exp2f(s[nt][3] - mn1); ls1 += s[nt][3];
        }
        ls0 += __shfl_xor_sync(0xffffffffu, ls0, 1);
        ls0 += __shfl_xor_sync(0xffffffffu, ls0, 2);
        ls1 += __shfl_xor_sync(0xffffffffu, ls1, 1);
        ls1 += __shfl_xor_sync(0xffffffffu, ls1, 2);
        l0 = l0 * cr0 + ls0;
        l1 = l1 * cr1 + ls1;
#pragma unroll
        for (int nt = 0; nt < 8; nt++) {
            o[nt][0] *= cr0; o[nt][1] *= cr0;
            o[nt][2] *= cr1; o[nt][3] *= cr1;
        }

#pragma unroll
        for (int kc = 0; kc < 4; kc++) {
            const int kb = kc * 16;
            uint32_t ph0, pl0, ph1, pl1, ph2, pl2, ph3, pl3;
            split_pack(s[2 * kc][0],     s[2 * kc][1],     ph0, pl0);
            split_pack(s[2 * kc][2],     s[2 * kc][3],     ph1, pl1);
            split_pack(s[2 * kc + 1][0], s[2 * kc + 1][1], ph2, pl2);
            split_pack(s[2 * kc + 1][2], s[2 * kc + 1][3], ph3, pl3);
#pragma unroll
            for (int nt = 0; nt < 8; nt++) {
                int n = nt * 8 + g;
                uint32_t vh0 = *(const uint32_t*)&Vh[n * AP + kb + 2 * tig];
                uint32_t vh1 = *(const uint32_t*)&Vh[n * AP + kb + 8 + 2 * tig];
                uint32_t vl0 = *(const uint32_t*)&Vl[n * AP + kb + 2 * tig];
                uint32_t vl1 = *(const uint32_t*)&Vl[n * AP + kb + 8 + 2 * tig];
                mma_bf16(o[nt], ph0, ph1, ph2, ph3, vh0, vh1);
                mma_bf16(o[nt], ph0, ph1, ph2, ph3, vl0, vl1);
                mma_bf16(o[nt], pl0, pl1, pl2, pl3, vh0, vh1);
            }
        }
        __syncthreads();
    }

    // Write unnormalized partials
    const int r = t0 + warp * 16 + g;
    float* po = g_po + (size_t)split * MTOT * HDIM;
#pragma unroll
    for (int nt = 0; nt < 8; nt++) {
        int col = nt * 8 + 2 * tig;
        *(float2*)&po[r * HDIM + col]       = make_float2(o[nt][0], o[nt][1]);
        *(float2*)&po[(r + 8) * HDIM + col] = make_float2(o[nt][2], o[nt][3]);
    }
    if (tig == 0) {
        g_pm[split * MTOT + r]     = m0;
        g_pm[split * MTOT + r + 8] = m1;
        g_pl[split * MTOT + r]     = l0;
        g_pl[split * MTOT + r + 8] = l1;
    }
}

// ---------------------------------------------------------------------------
// Kernel 3b: combine split-KV partials -> ctx (split bf16).
// Block 256 = 8 warps; warp owns one row (64 cols, 2 per lane). Grid 2048.
// ---------------------------------------------------------------------------
__global__ __launch_bounds__(256) void combine_kernel() {
    const int warp = threadIdx.x >> 5, lane = threadIdx.x & 31;
    const int row = blockIdx.x * 8 + warp;
    const int col = lane * 2;

    float m[NSPLIT], lpart[NSPLIT];
    float M = -1e30f;
#pragma unroll
    for (int i = 0; i < NSPLIT; i++) {
        m[i] = g_pm[i * MTOT + row];
        lpart[i] = g_pl[i * MTOT + row];
        M = fmaxf(M, m[i]);
    }
    float L = 0.f, w[NSPLIT];
#pragma unroll
    for (int i = 0; i < NSPLIT; i++) {
        w[i] = exp2f(m[i] - M);
        L += w[i] * lpart[i];
    }
    float inv = 1.0f / L;
    float c0 = 0.f, c1 = 0.f;
#pragma unroll
    for (int i = 0; i < NSPLIT; i++) {
        float2 ov = *(const float2*)&g_po[((size_t)i * MTOT + row) * HDIM + col];
        c0 += w[i] * ov.x;
        c1 += w[i] * ov.y;
    }
    uint32_t h, l;
    split_pack(c0 * inv, c1 * inv, h, l);
    *(uint32_t*)&g_chi[row * HDIM + col] = h;
    *(uint32_t*)&g_clo[row * HDIM + col] = l;
}

// ---------------------------------------------------------------------------
// Kernel 4: out = ctx[16384,64] @ Wo_sum[64,1024] + bo, split tensor-core MMA.
// ---------------------------------------------------------------------------
__global__ __launch_bounds__(256) void outproj_kernel(const float* __restrict__ bo,
                                                      float* __restrict__ out) {
    extern __shared__ __nv_bfloat16 sm[];
    __nv_bfloat16* Ash = sm;
    __nv_bfloat16* Asl = sm + 128 * AP;
    __nv_bfloat16* Bsh = sm + 2 * 128 * AP;
    __nv_bfloat16* Bsl = Bsh + 64 * AP;

    const int tid = threadIdx.x, warp = tid >> 5, lane = tid & 31;
    const int g = lane >> 2, tig = lane & 3;
    const int wm = warp & 3, wn = warp >> 2;
    const int row0 = blockIdx.x * 128, n0 = blockIdx.y * 64;

#pragma unroll
    for (int it = 0; it < 16; it++) {
        int id = tid + it * 256;
        int r = id >> 5, dp = (id & 31) * 2;
        *(uint32_t*)&Ash[r * AP + dp] = *(const uint32_t*)&g_chi[(row0 + r) * HDIM + dp];
        *(uint32_t*)&Asl[r * AP + dp] = *(const uint32_t*)&g_clo[(row0 + r) * HDIM + dp];
    }
#pragma unroll
    for (int it = 0; it < 8; it++) {
        int id = tid + it * 256;
        int n = id >> 5, dp = (id & 31) * 2;
        *(uint32_t*)&Bsh[n * AP + dp] = *(const uint32_t*)&g_wohi[(n0 + n) * HDIM + dp];
        *(uint32_t*)&Bsl[n * AP + dp] = *(const uint32_t*)&g_wolo[(n0 + n) * HDIM + dp];
    }
    __syncthreads();

    float c[2][4][4];
#pragma unroll
    for (int mt = 0; mt < 2; mt++)
#pragma unroll
        for (int nt = 0; nt < 4; nt++)
#pragma unroll
            for (int j = 0; j < 4; j++) c[mt][nt][j] = 0.f;

#pragma unroll
    for (int kc = 0; kc < 4; kc++) {
        const int kb = kc * 16;
        uint32_t ah[2][4], al[2][4];
#pragma unroll
        for (int mt = 0; mt < 2; mt++) {
            int r = wm * 32 + mt * 16 + g;
            ah[mt][0] = *(const uint32_t*)&Ash[r * AP + kb + 2 * tig];
            ah[mt][1] = *(const uint32_t*)&Ash[(r + 8) * AP + kb + 2 * tig];
            ah[mt][2] = *(const uint32_t*)&Ash[r * AP + kb + 8 + 2 * tig];
            ah[mt][3] = *(const uint32_t*)&Ash[(r + 8) * AP + kb + 8 + 2 * tig];
            al[mt][0] = *(const uint32_t*)&Asl[r * AP + kb + 2 * tig];
            al[mt][1] = *(const uint32_t*)&Asl[(r + 8) * AP + kb + 2 * tig];
            al[mt][2] = *(const uint32_t*)&Asl[r * AP + kb + 8 + 2 * tig];
            al[mt][3] = *(const uint32_t*)&Asl[(r + 8) * AP + kb + 8 + 2 * tig];
        }
#pragma unroll
        for (int nt = 0; nt < 4; nt++) {
            int n = wn * 32 + nt * 8 + g;
            uint32_t bh0 = *(const uint32_t*)&Bsh[n * AP + kb + 2 * tig];
            uint32_t bh1 = *(const uint32_t*)&Bsh[n * AP + kb + 8 + 2 * tig];
            uint32_t bl0 = *(const uint32_t*)&Bsl[n * AP + kb + 2 * tig];
            uint32_t bl1 = *(const uint32_t*)&Bsl[n * AP + kb + 8 + 2 * tig];
#pragma unroll
            for (int mt = 0; mt < 2; mt++) {
                mma_bf16(c[mt][nt], ah[mt][0], ah[mt][1], ah[mt][2], ah[mt][3], bh0, bh1);
                mma_bf16(c[mt][nt], ah[mt][0], ah[mt][1], ah[mt][2], ah[mt][3], bl0, bl1);
                mma_bf16(c[mt][nt], al[mt][0], al[mt][1], al[mt][2], al[mt][3], bh0, bh1);
            }
        }
    }

#pragma unroll
    for (int mt = 0; mt < 2; mt++) {
#pragma unroll
        for (int nt = 0; nt < 4; nt++) {
            int r   = row0 + wm * 32 + mt * 16 + g;
            int col = n0 + wn * 32 + nt * 8 + 2 * tig;
            float bv0 = bo[col], bv1 = bo[col + 1];
            float2 v0 = make_float2(c[mt][nt][0] + bv0, c[mt][nt][1] + bv1);
            float2 v1 = make_float2(c[mt][nt][2] + bv0, c[mt][nt][3] + bv1);
            *(float2*)&out[r * DMODEL + col] = v0;
            *(float2*)&out[(r + 8) * DMODEL + col] = v1;
        }
    }
}

// ---------------------------------------------------------------------------
extern "C" void kernel_launch(void* const* d_in, const int* in_sizes, int n_in,
                              void* d_out, int out_size) {
    const float* query = (const float*)d_in[0];
    const float* key   = (const float*)d_in[1];
    const float* value = (const float*)d_in[2];
    const float* Wq    = (const float*)d_in[3];
    const float* bq    = (const float*)d_in[4];
    const float* Wk    = (const float*)d_in[5];
    const float* bk    = (const float*)d_in[6];
    const float* Wv    = (const float*)d_in[7];
    const float* bv    = (const float*)d_in[8];
    const float* Wo    = (const float*)d_in[9];
    const float* bo    = (const float*)d_in[10];
    float* out = (float*)d_out;

    const int ATTN_SMEM = 6 * 64 * AP * (int)sizeof(__nv_bfloat16);             // 55296
    const int OUTP_SMEM = (2 * 128 + 2 * 64) * AP * (int)sizeof(__nv_bfloat16); // 55296
    cudaFuncSetAttribute(attn_kernel, cudaFuncAttributeMaxDynamicSharedMemorySize, ATTN_SMEM);
    cudaFuncSetAttribute(outproj_kernel, cudaFuncAttributeMaxDynamicSharedMemorySize, OUTP_SMEM);

    wosum_kernel<<<256, 256>>>(Wo);
    proj_kernel<<<dim3(128, 3), 256>>>(query, key, value,
                                       Wq, Wk, Wv, bq, bk, bv);
    attn_kernel<<<dim3(SS / 64, BB, NSPLIT), 128, ATTN_SMEM>>>();
    combine_kernel<<<MTOT / 8, 256>>>();
    outproj_kernel<<<dim3(MTOT / 128, DMODEL / 64), 256, OUTP_SMEM>>>(bo, out);
}

// round 5
// speedup vs baseline: 3.4969x; 2.0238x over previous
#include <cuda_runtime.h>
#include <cuda_fp16.h>
#include <cstdint>

// Problem dims
#define BB 8
#define SS 2048
#define DMODEL 1024
#define HDIM 64
#define NHEADS 16
#define MTOT (BB * SS)   // 16384 tokens
#define NSPLIT 4         // KV splits
#define KPS (SS / NSPLIT) // 512 keys per split

// ---------------------------------------------------------------------------
// Scratch (fp16 operands, fp32 partials).
// q,k,ctx: [token][64] row-major.  v: TRANSPOSED [b][dim][s].  wo: [n][d].
// ---------------------------------------------------------------------------
__device__ __half g_qh[MTOT * HDIM];
__device__ __half g_kh[MTOT * HDIM];
__device__ __half g_vh[MTOT * HDIM];     // [b][dim][s]
__device__ __half g_ch[MTOT * HDIM];
__device__ __half g_woh[DMODEL * HDIM];  // [n][d]
// Split-KV partials (fp32, unnormalized o; m,l in log2 domain)
__device__ float g_po[NSPLIT * MTOT * HDIM];
__device__ float g_pm[NSPLIT * MTOT];
__device__ float g_pl[NSPLIT * MTOT];

// ---------------------------------------------------------------------------
// Helpers
// ---------------------------------------------------------------------------
__device__ __forceinline__ void mma_fp16(float c[4],
                                         uint32_t a0, uint32_t a1, uint32_t a2, uint32_t a3,
                                         uint32_t b0, uint32_t b1) {
    asm volatile(
        "mma.sync.aligned.m16n8k16.row.col.f32.f16.f16.f32 "
        "{%0,%1,%2,%3}, {%4,%5,%6,%7}, {%8,%9}, {%0,%1,%2,%3};\n"
        : "+f"(c[0]), "+f"(c[1]), "+f"(c[2]), "+f"(c[3])
        : "r"(a0), "r"(a1), "r"(a2), "r"(a3), "r"(b0), "r"(b1));
}

__device__ __forceinline__ uint32_t pack2h(float x, float y) {
    __half2 h = __floats2half2_rn(x, y);
    return *reinterpret_cast<uint32_t*>(&h);
}

// ---------------------------------------------------------------------------
// Kernel 1: Wo_sum^T[n][d] = sum_h Wo[h*64+d][n]  (fp16)
// ---------------------------------------------------------------------------
__global__ void wosum_kernel(const float* __restrict__ Wo) {
    int idx = blockIdx.x * blockDim.x + threadIdx.x;   // 0..65535
    int d = idx >> 10;
    int n = idx & (DMODEL - 1);
    float s = 0.f;
#pragma unroll
    for (int h = 0; h < NHEADS; h++)
        s += Wo[(h * HDIM + d) * DMODEL + n];
    g_woh[n * HDIM + d] = __float2half_rn(s);
}

// ---------------------------------------------------------------------------
// Kernel 2: fused q/k/v projections (fp16 tensor-core MMA, fp32 accum).
// X[16384,1024] @ W[1024,64] + b.  BM=128, BN=64, BK=32. 256 thr, 8 warps.
// q scaled by 0.125*log2(e) (softmax runs in base-2); v written [b][dim][s].
// ---------------------------------------------------------------------------
#define PP 40   // smem pitch (halves)
#define QSCALE (0.125f * 1.4426950408889634f)
__global__ __launch_bounds__(256) void proj_kernel(
    const float* __restrict__ Xq, const float* __restrict__ Xk, const float* __restrict__ Xv,
    const float* __restrict__ Wq, const float* __restrict__ Wk, const float* __restrict__ Wv,
    const float* __restrict__ bq, const float* __restrict__ bk, const float* __restrict__ bv) {

    const int which = blockIdx.y;
    const float* X;  const float* W;  const float* bias;
    if (which == 0)      { X = Xq; W = Wq; bias = bq; }
    else if (which == 1) { X = Xk; W = Wk; bias = bk; }
    else                 { X = Xv; W = Wv; bias = bv; }

    __shared__ __half Ash[128][PP];
    __shared__ __half Bsh[64][PP];   // W transposed: [n][k]

    const int tid  = threadIdx.x;
    const int warp = tid >> 5, lane = tid & 31;
    const int g = lane >> 2, tig = lane & 3;
    const int wm = warp & 3, wn = warp >> 2;
    const int row0 = blockIdx.x * 128;

    float c[2][4][4];
#pragma unroll
    for (int mt = 0; mt < 2; mt++)
#pragma unroll
        for (int nt = 0; nt < 4; nt++)
#pragma unroll
            for (int j = 0; j < 4; j++) c[mt][nt][j] = 0.f;

    for (int k0 = 0; k0 < DMODEL; k0 += 32) {
        // Stage X tile 128x32
#pragma unroll
        for (int it = 0; it < 4; it++) {
            int id = tid + it * 256;              // 0..1023 float4s
            int r = id >> 3, cg = (id & 7) * 4;
            float4 x4 = *(const float4*)(X + (row0 + r) * DMODEL + k0 + cg);
            *(uint32_t*)&Ash[r][cg]     = pack2h(x4.x, x4.y);
            *(uint32_t*)&Ash[r][cg + 2] = pack2h(x4.z, x4.w);
        }
        // Stage W tile 32x64 transposed into [n][k]
#pragma unroll
        for (int it = 0; it < 2; it++) {
            int id = tid + it * 256;              // 0..511 float4s
            int kr = id >> 4, cg = (id & 15) * 4;
            float4 w4 = *(const float4*)(W + (k0 + kr) * HDIM + cg);
            Bsh[cg + 0][kr] = __float2half_rn(w4.x);
            Bsh[cg + 1][kr] = __float2half_rn(w4.y);
            Bsh[cg + 2][kr] = __float2half_rn(w4.z);
            Bsh[cg + 3][kr] = __float2half_rn(w4.w);
        }
        __syncthreads();

#pragma unroll
        for (int kk = 0; kk < 2; kk++) {
            const int kb = kk * 16;
            uint32_t ah[2][4];
#pragma unroll
            for (int mt = 0; mt < 2; mt++) {
                int r = wm * 32 + mt * 16 + g;
                ah[mt][0] = *(const uint32_t*)&Ash[r    ][kb + 2 * tig];
                ah[mt][1] = *(const uint32_t*)&Ash[r + 8][kb + 2 * tig];
                ah[mt][2] = *(const uint32_t*)&Ash[r    ][kb + 8 + 2 * tig];
                ah[mt][3] = *(const uint32_t*)&Ash[r + 8][kb + 8 + 2 * tig];
            }
#pragma unroll
            for (int nt = 0; nt < 4; nt++) {
                int n = wn * 32 + nt * 8 + g;
                uint32_t bh0 = *(const uint32_t*)&Bsh[n][kb + 2 * tig];
                uint32_t bh1 = *(const uint32_t*)&Bsh[n][kb + 8 + 2 * tig];
#pragma unroll
                for (int mt = 0; mt < 2; mt++)
                    mma_fp16(c[mt][nt], ah[mt][0], ah[mt][1], ah[mt][2], ah[mt][3], bh0, bh1);
            }
        }
        __syncthreads();
    }

    const float scale = (which == 0) ? QSCALE : 1.0f;
    __half* oh = (which == 0) ? g_qh : g_kh;

#pragma unroll
    for (int mt = 0; mt < 2; mt++) {
#pragma unroll
        for (int nt = 0; nt < 4; nt++) {
            int r   = row0 + wm * 32 + mt * 16 + g;
            int col = wn * 32 + nt * 8 + 2 * tig;
            float bv0 = bias[col], bv1 = bias[col + 1];
            float v0 = (c[mt][nt][0] + bv0) * scale;
            float v1 = (c[mt][nt][1] + bv1) * scale;
            float v2 = (c[mt][nt][2] + bv0) * scale;   // row r+8
            float v3 = (c[mt][nt][3] + bv1) * scale;
            if (which < 2) {
                *(uint32_t*)&oh[r * HDIM + col]       = pack2h(v0, v1);
                *(uint32_t*)&oh[(r + 8) * HDIM + col] = pack2h(v2, v3);
            } else {
                // v transposed: [b][dim][s]
                int b = r >> 11, s = r & 2047;
                g_vh[(b * HDIM + col) * SS + s]         = __float2half_rn(v0);
                g_vh[(b * HDIM + col + 1) * SS + s]     = __float2half_rn(v1);
                g_vh[(b * HDIM + col) * SS + s + 8]     = __float2half_rn(v2);
                g_vh[(b * HDIM + col + 1) * SS + s + 8] = __float2half_rn(v3);
            }
        }
    }
}

// ---------------------------------------------------------------------------
// Kernel 3: split-KV flash attention (fp16 tensor cores).
// grid (S/64, B, NSPLIT); block 128 (4 warps, warp owns 16 q-rows).
// Each block: 64 q-rows x 512 keys; writes unnormalized partial (o, m, l).
// Softmax in base-2 (scores pre-scaled by log2 e) -> pure exp2f.
// ---------------------------------------------------------------------------
#define AP 72   // smem pitch (halves)
__global__ __launch_bounds__(128) void attn_kernel() {
    extern __shared__ __half sm[];
    __half* Qh = sm;
    __half* Kh = sm + 1 * 64 * AP;
    __half* Vh = sm + 2 * 64 * AP;

    const int tid = threadIdx.x, warp = tid >> 5, lane = tid & 31;
    const int g = lane >> 2, tig = lane & 3;
    const int bq = blockIdx.x, b = blockIdx.y, split = blockIdx.z;
    const int t0 = b * SS + bq * 64;
    const int kt0 = split * (KPS / 64);

#pragma unroll
    for (int it = 0; it < 16; it++) {
        int id = tid + it * 128;                 // 0..2047 u32s
        int r = id >> 5, dp = (id & 31) * 2;
        *(uint32_t*)&Qh[r * AP + dp] = *(const uint32_t*)&g_qh[(t0 + r) * HDIM + dp];
    }

    float m0 = -1e30f, m1 = -1e30f, l0 = 0.f, l1 = 0.f;
    float o[8][4];
#pragma unroll
    for (int nt = 0; nt < 8; nt++)
#pragma unroll
        for (int j = 0; j < 4; j++) o[nt][j] = 0.f;

    const __half* kb_ = g_kh + (size_t)b * SS * HDIM;
    const __half* vb_ = g_vh + (size_t)b * HDIM * SS;

    for (int kt = kt0; kt < kt0 + KPS / 64; kt++) {
#pragma unroll
        for (int it = 0; it < 16; it++) {
            int id = tid + it * 128;
            int r = id >> 5, dp = (id & 31) * 2;
            *(uint32_t*)&Kh[r * AP + dp] = *(const uint32_t*)&kb_[(kt * 64 + r) * HDIM + dp];
            *(uint32_t*)&Vh[r * AP + dp] = *(const uint32_t*)&vb_[r * SS + kt * 64 + dp];
        }
        __syncthreads();

        // S = Q K^T
        float s[8][4];
#pragma unroll
        for (int nt = 0; nt < 8; nt++)
#pragma unroll
            for (int j = 0; j < 4; j++) s[nt][j] = 0.f;

#pragma unroll
        for (int kc = 0; kc < 4; kc++) {
            const int kb = kc * 16;
            const int r = warp * 16 + g;
            uint32_t qh0 = *(const uint32_t*)&Qh[r * AP + kb + 2 * tig];
            uint32_t qh1 = *(const uint32_t*)&Qh[(r + 8) * AP + kb + 2 * tig];
            uint32_t qh2 = *(const uint32_t*)&Qh[r * AP + kb + 8 + 2 * tig];
            uint32_t qh3 = *(const uint32_t*)&Qh[(r + 8) * AP + kb + 8 + 2 * tig];
#pragma unroll
            for (int nt = 0; nt < 8; nt++) {
                int n = nt * 8 + g;
                uint32_t kh0 = *(const uint32_t*)&Kh[n * AP + kb + 2 * tig];
                uint32_t kh1 = *(const uint32_t*)&Kh[n * AP + kb + 8 + 2 * tig];
                mma_fp16(s[nt], qh0, qh1, qh2, qh3, kh0, kh1);
            }
        }

        // Online softmax, base-2 domain
        float mt0 = -1e30f, mt1 = -1e30f;
#pragma unroll
        for (int nt = 0; nt < 8; nt++) {
            mt0 = fmaxf(mt0, fmaxf(s[nt][0], s[nt][1]));
            mt1 = fmaxf(mt1, fmaxf(s[nt][2], s[nt][3]));
        }
        mt0 = fmaxf(mt0, __shfl_xor_sync(0xffffffffu, mt0, 1));
        mt0 = fmaxf(mt0, __shfl_xor_sync(0xffffffffu, mt0, 2));
        mt1 = fmaxf(mt1, __shfl_xor_sync(0xffffffffu, mt1, 1));
        mt1 = fmaxf(mt1, __shfl_xor_sync(0xffffffffu, mt1, 2));
        float mn0 = fmaxf(m0, mt0), mn1 = fmaxf(m1, mt1);
        float cr0 = exp2f(m0 - mn0), cr1 = exp2f(m1 - mn1);
        m0 = mn0; m1 = mn1;
        float ls0 = 0.f, ls1 = 0.f;
#pragma unroll
        for (int nt = 0; nt < 8; nt++) {
            s[nt][0] = exp2f(s[nt][0] - mn0); ls0 += s[nt][0];
            s[nt][1] = exp2f(s[nt][1] - mn0); ls0 += s[nt][1];
            s[nt][2] = exp2f(s[nt][2] - mn1); ls1 += s[nt][2];
            s[nt][3] = exp2f(s[nt][3] - mn1); ls1 += s[nt][3];
        }
        ls0 += __shfl_xor_sync(0xffffffffu, ls0, 1);
        ls0 += __shfl_xor_sync(0xffffffffu, ls0, 2);
        ls1 += __shfl_xor_sync(0xffffffffu, ls1, 1);
        ls1 += __shfl_xor_sync(0xffffffffu, ls1, 2);
        l0 = l0 * cr0 + ls0;
        l1 = l1 * cr1 + ls1;
#pragma unroll
        for (int nt = 0; nt < 8; nt++) {
            o[nt][0] *= cr0; o[nt][1] *= cr0;
            o[nt][2] *= cr1; o[nt][3] *= cr1;
        }

        // ctx += P V  (P fragments straight from accumulators)
#pragma unroll
        for (int kc = 0; kc < 4; kc++) {
            const int kb = kc * 16;
            uint32_t ph0 = pack2h(s[2 * kc][0],     s[2 * kc][1]);
            uint32_t ph1 = pack2h(s[2 * kc][2],     s[2 * kc][3]);
            uint32_t ph2 = pack2h(s[2 * kc + 1][0], s[2 * kc + 1][1]);
            uint32_t ph3 = pack2h(s[2 * kc + 1][2], s[2 * kc + 1][3]);
#pragma unroll
            for (int nt = 0; nt < 8; nt++) {
                int n = nt * 8 + g;
                uint32_t vh0 = *(const uint32_t*)&Vh[n * AP + kb + 2 * tig];
                uint32_t vh1 = *(const uint32_t*)&Vh[n * AP + kb + 8 + 2 * tig];
                mma_fp16(o[nt], ph0, ph1, ph2, ph3, vh0, vh1);
            }
        }
        __syncthreads();
    }

    // Write unnormalized partials
    const int r = t0 + warp * 16 + g;
    float* po = g_po + (size_t)split * MTOT * HDIM;
#pragma unroll
    for (int nt = 0; nt < 8; nt++) {
        int col = nt * 8 + 2 * tig;
        *(float2*)&po[r * HDIM + col]       = make_float2(o[nt][0], o[nt][1]);
        *(float2*)&po[(r + 8) * HDIM + col] = make_float2(o[nt][2], o[nt][3]);
    }
    if (tig == 0) {
        g_pm[split * MTOT + r]     = m0;
        g_pm[split * MTOT + r + 8] = m1;
        g_pl[split * MTOT + r]     = l0;
        g_pl[split * MTOT + r + 8] = l1;
    }
}

// ---------------------------------------------------------------------------
// Kernel 3b: combine split-KV partials -> ctx (fp16).
// Block 256 = 8 warps; warp owns one row (64 cols, 2 per lane). Grid 2048.
// ---------------------------------------------------------------------------
__global__ __launch_bounds__(256) void combine_kernel() {
    const int warp = threadIdx.x >> 5, lane = threadIdx.x & 31;
    const int row = blockIdx.x * 8 + warp;
    const int col = lane * 2;

    float m[NSPLIT], lpart[NSPLIT];
    float M = -1e30f;
#pragma unroll
    for (int i = 0; i < NSPLIT; i++) {
        m[i] = g_pm[i * MTOT + row];
        lpart[i] = g_pl[i * MTOT + row];
        M = fmaxf(M, m[i]);
    }
    float L = 0.f, w[NSPLIT];
#pragma unroll
    for (int i = 0; i < NSPLIT; i++) {
        w[i] = exp2f(m[i] - M);
        L += w[i] * lpart[i];
    }
    float inv = 1.0f / L;
    float c0 = 0.f, c1 = 0.f;
#pragma unroll
    for (int i = 0; i < NSPLIT; i++) {
        float2 ov = *(const float2*)&g_po[((size_t)i * MTOT + row) * HDIM + col];
        c0 += w[i] * ov.x;
        c1 += w[i] * ov.y;
    }
    *(uint32_t*)&g_ch[row * HDIM + col] = pack2h(c0 * inv, c1 * inv);
}

// ---------------------------------------------------------------------------
// Kernel 4: out = ctx[16384,64] @ Wo_sum[64,1024] + bo (fp16 MMA).
// BM=128, BN=64, K=64. 256 thr, 8 warps (4x2), warp tile 32x32.
// ---------------------------------------------------------------------------
__global__ __launch_bounds__(256) void outproj_kernel(const float* __restrict__ bo,
                                                      float* __restrict__ out) {
    extern __shared__ __half sm[];
    __half* Ash = sm;              // ctx [128][AP]
    __half* Bsh = sm + 128 * AP;   // woT [64][AP]

    const int tid = threadIdx.x, warp = tid >> 5, lane = tid & 31;
    const int g = lane >> 2, tig = lane & 3;
    const int wm = warp & 3, wn = warp >> 2;
    const int row0 = blockIdx.x * 128, n0 = blockIdx.y * 64;

#pragma unroll
    for (int it = 0; it < 16; it++) {
        int id = tid + it * 256;                  // 0..4095 u32s
        int r = id >> 5, dp = (id & 31) * 2;
        *(uint32_t*)&Ash[r * AP + dp] = *(const uint32_t*)&g_ch[(row0 + r) * HDIM + dp];
    }
#pragma unroll
    for (int it = 0; it < 8; it++) {
        int id = tid + it * 256;                  // 0..2047 u32s
        int n = id >> 5, dp = (id & 31) * 2;
        *(uint32_t*)&Bsh[n * AP + dp] = *(const uint32_t*)&g_woh[(n0 + n) * HDIM + dp];
    }
    __syncthreads();

    float c[2][4][4];
#pragma unroll
    for (int mt = 0; mt < 2; mt++)
#pragma unroll
        for (int nt = 0; nt < 4; nt++)
#pragma unroll
            for (int j = 0; j < 4; j++) c[mt][nt][j] = 0.f;

#pragma unroll
    for (int kc = 0; kc < 4; kc++) {
        const int kb = kc * 16;
        uint32_t ah[2][4];
#pragma unroll
        for (int mt = 0; mt < 2; mt++) {
            int r = wm * 32 + mt * 16 + g;
            ah[mt][0] = *(const uint32_t*)&Ash[r * AP + kb + 2 * tig];
            ah[mt][1] = *(const uint32_t*)&Ash[(r + 8) * AP + kb + 2 * tig];
            ah[mt][2] = *(const uint32_t*)&Ash[r * AP + kb + 8 + 2 * tig];
            ah[mt][3] = *(const uint32_t*)&Ash[(r + 8) * AP + kb + 8 + 2 * tig];
        }
#pragma unroll
        for (int nt = 0; nt < 4; nt++) {
            int n = wn * 32 + nt * 8 + g;
            uint32_t bh0 = *(const uint32_t*)&Bsh[n * AP + kb + 2 * tig];
            uint32_t bh1 = *(const uint32_t*)&Bsh[n * AP + kb + 8 + 2 * tig];
#pragma unroll
            for (int mt = 0; mt < 2; mt++)
                mma_fp16(c[mt][nt], ah[mt][0], ah[mt][1], ah[mt][2], ah[mt][3], bh0, bh1);
        }
    }

#pragma unroll
    for (int mt = 0; mt < 2; mt++) {
#pragma unroll
        for (int nt = 0; nt < 4; nt++) {
            int r   = row0 + wm * 32 + mt * 16 + g;
            int col = n0 + wn * 32 + nt * 8 + 2 * tig;
            float bv0 = bo[col], bv1 = bo[col + 1];
            float2 v0 = make_float2(c[mt][nt][0] + bv0, c[mt][nt][1] + bv1);
            float2 v1 = make_float2(c[mt][nt][2] + bv0, c[mt][nt][3] + bv1);
            *(float2*)&out[r * DMODEL + col] = v0;
            *(float2*)&out[(r + 8) * DMODEL + col] = v1;
        }
    }
}

// ---------------------------------------------------------------------------
extern "C" void kernel_launch(void* const* d_in, const int* in_sizes, int n_in,
                              void* d_out, int out_size) {
    const float* query = (const float*)d_in[0];
    const float* key   = (const float*)d_in[1];
    const float* value = (const float*)d_in[2];
    const float* Wq    = (const float*)d_in[3];
    const float* bq    = (const float*)d_in[4];
    const float* Wk    = (const float*)d_in[5];
    const float* bk    = (const float*)d_in[6];
    const float* Wv    = (const float*)d_in[7];
    const float* bv    = (const float*)d_in[8];
    const float* Wo    = (const float*)d_in[9];
    const float* bo    = (const float*)d_in[10];
    float* out = (float*)d_out;

    const int ATTN_SMEM = 3 * 64 * AP * (int)sizeof(__half);           // 27648
    const int OUTP_SMEM = (128 + 64) * AP * (int)sizeof(__half);       // 27648

    wosum_kernel<<<256, 256>>>(Wo);
    proj_kernel<<<dim3(128, 3), 256>>>(query, key, value,
                                       Wq, Wk, Wv, bq, bk, bv);
    attn_kernel<<<dim3(SS / 64, BB, NSPLIT), 128, ATTN_SMEM>>>();
    combine_kernel<<<MTOT / 8, 256>>>();
    outproj_kernel<<<dim3(MTOT / 128, DMODEL / 64), 256, OUTP_SMEM>>>(bo, out);
}